// round 6
// baseline (speedup 1.0000x reference)
#include <cuda_runtime.h>

// Warp3d: out[n, h, w, d] = trilinear_sample(x[n], grid + flow[n]),
// zeros padding, per the JAX reference. fp32 throughout.
//
// R6: move gathers from L1tex (78.8% busy in R5) into shared memory.
// Each block stages a 24x24x96 volume neighborhood (halo +-4) for a
// 16x16x80 output tile; >99.9% of samples gather from smem, rare
// out-of-tile/out-of-volume samples use the exact global fallback.

constexpr int H = 160, W = 192, D = 160;
constexpr int WD  = W * D;           // 30720
constexpr int HWD = H * WD;          // 4915200

constexpr int TH = 16, TW = 16, TD = 80;
constexpr int HALO = 4;
constexpr int SH = TH + 2 * HALO;    // 24
constexpr int SW = TW + 2 * HALO;    // 24
constexpr int SD = 96;               // z coverage: [d0-8, d0+87]
constexpr int SROW = 100;            // padded y-row stride (floats), 16B mult
constexpr int SXS  = SW * SROW;      // x stride = 2400 floats
constexpr int SMEM_FLOATS = SH * SXS;          // 57600
constexpr int SMEM_BYTES  = SMEM_FLOATS * 4;   // 230400

constexpr int NT_H = H / TH, NT_W = W / TW, NT_D = D / TD;  // 10, 12, 2
constexpr int TILES_PER_MAP = NT_H * NT_W * NT_D;           // 240
constexpr int NBLOCKS = 3 * TILES_PER_MAP;                  // 720
constexpr int SAMPLES_PER_TILE = TH * TW * TD;              // 20480
constexpr int NTHREADS = 256;
constexpr int ITERS = SAMPLES_PER_TILE / NTHREADS;          // 80

__device__ __forceinline__ float corner_load(const float* __restrict__ vol,
                                             int ix, int iy, int iz) {
    bool valid = ((unsigned)ix < (unsigned)H) &
                 ((unsigned)iy < (unsigned)W) &
                 ((unsigned)iz < (unsigned)D);
    int cx = min(max(ix, 0), H - 1);
    int cy = min(max(iy, 0), W - 1);
    int cz = min(max(iz, 0), D - 1);
    float v = __ldg(vol + (long)cx * WD + cy * D + cz);
    return valid ? v : 0.0f;
}

__global__ __launch_bounds__(NTHREADS)
void warp3d_tiled_kernel(const float* __restrict__ xin,
                         const float* __restrict__ win,
                         float* __restrict__ out) {
    extern __shared__ float smem[];

    int b = blockIdx.x;
    int n  = b / TILES_PER_MAP;
    int tr = b % TILES_PER_MAP;
    int td = tr % NT_D;
    int twt = (tr / NT_D) % NT_W;
    int tht = tr / (NT_D * NT_W);

    int h0 = tht * TH;
    int w0 = twt * TW;
    int d0 = td * TD;
    int zb = d0 - 8;                 // 16B-aligned z base (-8 or 72)

    const float* vol = xin + (long)n * HWD;
    const float* fw  = win + (long)n * 3 * HWD;

    int tid = threadIdx.x;

    // ---- Stage tile into smem (float4 chunks; OOB chunks are whole & zeroed,
    //      and are never consumed by the fast path). 13824 chunks / 256 thr.
    constexpr int NCHUNK = SH * SW * (SD / 4);    // 13824
    for (int c = tid; c < NCHUNK; c += NTHREADS) {
        int k  = c % (SD / 4);
        int yy = (c / (SD / 4)) % SW;
        int xx = c / ((SD / 4) * SW);
        int gx = h0 - HALO + xx;
        int gy = w0 - HALO + yy;
        int gz = zb + 4 * k;
        bool ok = ((unsigned)gx < (unsigned)H) &
                  ((unsigned)gy < (unsigned)W) &
                  (gz >= 0) & (gz + 3 < D);
        float4 v = make_float4(0.f, 0.f, 0.f, 0.f);
        if (ok) v = *(const float4*)(vol + (long)gx * WD + gy * D + gz);
        *(float4*)(smem + xx * SXS + yy * SROW + 4 * k) = v;
    }
    __syncthreads();

    // ---- Sample loop: sample s = i*256 + tid; lanes get consecutive d
    //      (stride-1 smem banks, coalesced flow/out).
    #pragma unroll 2
    for (int i = 0; i < ITERS; i++) {
        int s  = i * NTHREADS + tid;
        int dd = s % TD;
        int ww = (s / TD) % TW;
        int hh = s / (TD * TW);

        int h = h0 + hh, wv = w0 + ww, d = d0 + dd;
        long off = (long)h * WD + wv * D + d;

        float cx = (float)h  + __ldg(fw + off);
        float cy = (float)wv + __ldg(fw + HWD + off);
        float cz = (float)d  + __ldg(fw + 2L * HWD + off);

        float x0f = floorf(cx), y0f = floorf(cy), z0f = floorf(cz);
        float fx = cx - x0f, fy = cy - y0f, fz = cz - z0f;
        int x0 = (int)x0f, y0 = (int)y0f, z0 = (int)z0f;
        float gx0 = 1.0f - fx, gy0 = 1.0f - fy, gz0 = 1.0f - fz;

        float2 a00, a01, a10, a11;

        int xr = x0 - (h0 - HALO);
        int yr = y0 - (w0 - HALO);
        int zr = z0 - zb;
        bool global_ok = ((unsigned)x0 < (unsigned)(H - 1)) &
                         ((unsigned)y0 < (unsigned)(W - 1)) &
                         ((unsigned)z0 < (unsigned)(D - 1));
        bool tile_ok = ((unsigned)xr < (unsigned)(SH - 1)) &
                       ((unsigned)yr < (unsigned)(SW - 1)) &
                       ((unsigned)zr < (unsigned)(SD - 1));

        if (global_ok & tile_ok) {
            int za = zr & ~1;
            bool zodd = (zr & 1) != 0;
            const float* p = smem + xr * SXS + yr * SROW + za;

            float2 e00 = *(const float2*)(p);
            float2 e01 = *(const float2*)(p + SROW);
            float2 e10 = *(const float2*)(p + SXS);
            float2 e11 = *(const float2*)(p + SXS + SROW);

            float2 h00 = e00, h01 = e01, h10 = e10, h11 = e11;
            if (zodd) {
                h00 = *(const float2*)(p + 2);
                h01 = *(const float2*)(p + SROW + 2);
                h10 = *(const float2*)(p + SXS + 2);
                h11 = *(const float2*)(p + SXS + SROW + 2);
            }
            a00 = zodd ? make_float2(e00.y, h00.x) : e00;
            a01 = zodd ? make_float2(e01.y, h01.x) : e01;
            a10 = zodd ? make_float2(e10.y, h10.x) : e10;
            a11 = zodd ? make_float2(e11.y, h11.x) : e11;
        } else {
            int x1 = x0 + 1, y1 = y0 + 1, z1 = z0 + 1;
            a00.x = corner_load(vol, x0, y0, z0);
            a00.y = corner_load(vol, x0, y0, z1);
            a01.x = corner_load(vol, x0, y1, z0);
            a01.y = corner_load(vol, x0, y1, z1);
            a10.x = corner_load(vol, x1, y0, z0);
            a10.y = corner_load(vol, x1, y0, z1);
            a11.x = corner_load(vol, x1, y1, z0);
            a11.y = corner_load(vol, x1, y1, z1);
        }

        float c00 = a00.x * gz0 + a00.y * fz;
        float c01 = a01.x * gz0 + a01.y * fz;
        float c10 = a10.x * gz0 + a10.y * fz;
        float c11 = a11.x * gz0 + a11.y * fz;
        float c0  = c00 * gy0 + c01 * fy;
        float c1  = c10 * gy0 + c11 * fy;
        out[(long)n * HWD + off] = c0 * gx0 + c1 * fx;
    }
}

extern "C" void kernel_launch(void* const* d_in, const int* in_sizes, int n_in,
                              void* d_out, int out_size) {
    const float* x = (const float*)d_in[0];
    const float* w = (const float*)d_in[1];
    // x has 3*HWD elements, w has 9*HWD; swap defensively if order differs.
    if (n_in >= 2 && in_sizes[0] > in_sizes[1]) {
        const float* tmp = x; x = w; w = tmp;
    }
    float* out = (float*)d_out;

    cudaFuncSetAttribute(warp3d_tiled_kernel,
                         cudaFuncAttributeMaxDynamicSharedMemorySize,
                         SMEM_BYTES);
    warp3d_tiled_kernel<<<NBLOCKS, NTHREADS, SMEM_BYTES>>>(x, w, out);
}

// round 7
// speedup vs baseline: 2.6577x; 2.6577x over previous
#include <cuda_runtime.h>

// Warp3d: out[n, h, w, d] = trilinear_sample(x[n], grid + flow[n]),
// zeros padding, per the JAX reference. fp32 throughout.
//
// R7: R6's smem-gather design was right but occupancy-starved (8 warps/SM,
// occ 12%). Same 24x24x96 tile per block, now with 1024 threads/block
// (32 warps/SM) and an x-slice stride padded to break bank aliasing.

constexpr int H = 160, W = 192, D = 160;
constexpr int WD  = W * D;           // 30720
constexpr int HWD = H * WD;          // 4915200

constexpr int TH = 16, TW = 16, TD = 80;
constexpr int HALO = 4;
constexpr int SH = TH + 2 * HALO;    // 24
constexpr int SW = TW + 2 * HALO;    // 24
constexpr int SD = 96;               // z coverage: [d0-8, d0+87]
constexpr int SROW = 100;            // padded y-row stride (floats), 16B mult
constexpr int SXS  = SW * SROW + 8;  // x stride = 2408 floats (mod 32 = 8)
constexpr int SMEM_FLOATS = SH * SXS;          // 57792
constexpr int SMEM_BYTES  = SMEM_FLOATS * 4;   // 231168 (< 227 KB cap)

constexpr int NT_H = H / TH, NT_W = W / TW, NT_D = D / TD;  // 10, 12, 2
constexpr int TILES_PER_MAP = NT_H * NT_W * NT_D;           // 240
constexpr int NBLOCKS = 3 * TILES_PER_MAP;                  // 720
constexpr int SAMPLES_PER_TILE = TH * TW * TD;              // 20480
constexpr int NTHREADS = 1024;
constexpr int ITERS = SAMPLES_PER_TILE / NTHREADS;          // 20

__device__ __forceinline__ float corner_load(const float* __restrict__ vol,
                                             int ix, int iy, int iz) {
    bool valid = ((unsigned)ix < (unsigned)H) &
                 ((unsigned)iy < (unsigned)W) &
                 ((unsigned)iz < (unsigned)D);
    int cx = min(max(ix, 0), H - 1);
    int cy = min(max(iy, 0), W - 1);
    int cz = min(max(iz, 0), D - 1);
    float v = __ldg(vol + (long)cx * WD + cy * D + cz);
    return valid ? v : 0.0f;
}

__global__ __launch_bounds__(NTHREADS)
void warp3d_tiled_kernel(const float* __restrict__ xin,
                         const float* __restrict__ win,
                         float* __restrict__ out) {
    extern __shared__ float smem[];

    int b = blockIdx.x;
    int n  = b / TILES_PER_MAP;
    int tr = b % TILES_PER_MAP;
    int td = tr % NT_D;
    int twt = (tr / NT_D) % NT_W;
    int tht = tr / (NT_D * NT_W);

    int h0 = tht * TH;
    int w0 = twt * TW;
    int d0 = td * TD;
    int zb = d0 - 8;                 // 16B-aligned z base (-8 or 72)

    const float* vol = xin + (long)n * HWD;
    const float* fw  = win + (long)n * 3 * HWD;

    int tid = threadIdx.x;

    // ---- Stage tile into smem (float4 chunks; OOB chunks are whole & zeroed,
    //      and never consumed by the fast path). 13824 chunks / 1024 threads.
    constexpr int NCHUNK = SH * SW * (SD / 4);    // 13824
    for (int c = tid; c < NCHUNK; c += NTHREADS) {
        int k  = c % (SD / 4);
        int yy = (c / (SD / 4)) % SW;
        int xx = c / ((SD / 4) * SW);
        int gx = h0 - HALO + xx;
        int gy = w0 - HALO + yy;
        int gz = zb + 4 * k;
        bool ok = ((unsigned)gx < (unsigned)H) &
                  ((unsigned)gy < (unsigned)W) &
                  (gz >= 0) & (gz + 3 < D);
        float4 v = make_float4(0.f, 0.f, 0.f, 0.f);
        if (ok) v = *(const float4*)(vol + (long)gx * WD + gy * D + gz);
        *(float4*)(smem + xx * SXS + yy * SROW + 4 * k) = v;
    }
    __syncthreads();

    // ---- Sample loop: sample s = i*1024 + tid; lanes get consecutive d
    //      (spread smem banks, coalesced flow/out).
    #pragma unroll 2
    for (int i = 0; i < ITERS; i++) {
        int s  = i * NTHREADS + tid;
        int dd = s % TD;
        int ww = (s / TD) % TW;
        int hh = s / (TD * TW);

        int h = h0 + hh, wv = w0 + ww, d = d0 + dd;
        long off = (long)h * WD + wv * D + d;

        float cx = (float)h  + __ldg(fw + off);
        float cy = (float)wv + __ldg(fw + HWD + off);
        float cz = (float)d  + __ldg(fw + 2L * HWD + off);

        float x0f = floorf(cx), y0f = floorf(cy), z0f = floorf(cz);
        float fx = cx - x0f, fy = cy - y0f, fz = cz - z0f;
        int x0 = (int)x0f, y0 = (int)y0f, z0 = (int)z0f;
        float gx0 = 1.0f - fx, gy0 = 1.0f - fy, gz0 = 1.0f - fz;

        float2 a00, a01, a10, a11;

        int xr = x0 - (h0 - HALO);
        int yr = y0 - (w0 - HALO);
        int zr = z0 - zb;
        bool global_ok = ((unsigned)x0 < (unsigned)(H - 1)) &
                         ((unsigned)y0 < (unsigned)(W - 1)) &
                         ((unsigned)z0 < (unsigned)(D - 1));
        bool tile_ok = ((unsigned)xr < (unsigned)(SH - 1)) &
                       ((unsigned)yr < (unsigned)(SW - 1)) &
                       ((unsigned)zr < (unsigned)(SD - 1));

        if (global_ok & tile_ok) {
            int za = zr & ~1;
            bool zodd = (zr & 1) != 0;
            const float* p = smem + xr * SXS + yr * SROW + za;

            float2 e00 = *(const float2*)(p);
            float2 e01 = *(const float2*)(p + SROW);
            float2 e10 = *(const float2*)(p + SXS);
            float2 e11 = *(const float2*)(p + SXS + SROW);

            float2 h00 = e00, h01 = e01, h10 = e10, h11 = e11;
            if (zodd) {
                h00 = *(const float2*)(p + 2);
                h01 = *(const float2*)(p + SROW + 2);
                h10 = *(const float2*)(p + SXS + 2);
                h11 = *(const float2*)(p + SXS + SROW + 2);
            }
            a00 = zodd ? make_float2(e00.y, h00.x) : e00;
            a01 = zodd ? make_float2(e01.y, h01.x) : e01;
            a10 = zodd ? make_float2(e10.y, h10.x) : e10;
            a11 = zodd ? make_float2(e11.y, h11.x) : e11;
        } else {
            int x1 = x0 + 1, y1 = y0 + 1, z1 = z0 + 1;
            a00.x = corner_load(vol, x0, y0, z0);
            a00.y = corner_load(vol, x0, y0, z1);
            a01.x = corner_load(vol, x0, y1, z0);
            a01.y = corner_load(vol, x0, y1, z1);
            a10.x = corner_load(vol, x1, y0, z0);
            a10.y = corner_load(vol, x1, y0, z1);
            a11.x = corner_load(vol, x1, y1, z0);
            a11.y = corner_load(vol, x1, y1, z1);
        }

        float c00 = a00.x * gz0 + a00.y * fz;
        float c01 = a01.x * gz0 + a01.y * fz;
        float c10 = a10.x * gz0 + a10.y * fz;
        float c11 = a11.x * gz0 + a11.y * fz;
        float c0  = c00 * gy0 + c01 * fy;
        float c1  = c10 * gy0 + c11 * fy;
        out[(long)n * HWD + off] = c0 * gx0 + c1 * fx;
    }
}

extern "C" void kernel_launch(void* const* d_in, const int* in_sizes, int n_in,
                              void* d_out, int out_size) {
    const float* x = (const float*)d_in[0];
    const float* w = (const float*)d_in[1];
    // x has 3*HWD elements, w has 9*HWD; swap defensively if order differs.
    if (n_in >= 2 && in_sizes[0] > in_sizes[1]) {
        const float* tmp = x; x = w; w = tmp;
    }
    float* out = (float*)d_out;

    cudaFuncSetAttribute(warp3d_tiled_kernel,
                         cudaFuncAttributeMaxDynamicSharedMemorySize,
                         SMEM_BYTES);
    warp3d_tiled_kernel<<<NBLOCKS, NTHREADS, SMEM_BYTES>>>(x, w, out);
}

// round 8
// speedup vs baseline: 2.7696x; 1.0421x over previous
#include <cuda_runtime.h>

// Warp3d: out[n, h, w, d] = trilinear_sample(x[n], grid + flow[n]),
// zeros padding, per the JAX reference. fp32 throughout.
//
// R8: smem-tiled gather with OVERLAP. R7 failed because 225KB smem forced
// 1 block/SM (staging serialized with compute). Now: 16x8x40 tile, staged
// 24x16x56 = 84.75KB -> 2 blocks/SM (32 warps), ~10 waves so staging of one
// block hides behind sampling of another. Gathers are 8 plain LDS.32.

constexpr int H = 160, W = 192, D = 160;
constexpr int WD  = W * D;           // 30720
constexpr int HWD = H * WD;          // 4915200

constexpr int TH = 16, TW = 8, TD = 40;
constexpr int HALO = 4;
constexpr int SH = TH + 2 * HALO;    // 24
constexpr int SW = TW + 2 * HALO;    // 16
constexpr int SD = 56;               // z coverage [d0-8, d0+47]
constexpr int SYS = SD;              // y stride (floats) = 56
constexpr int SXS = SW * SD + 8;     // x stride = 904 (mod 32 = 8, breaks aliasing)
constexpr int SMEM_FLOATS = SH * SXS;          // 21696
constexpr int SMEM_BYTES  = SMEM_FLOATS * 4;   // 86784 (~84.75 KB)

constexpr int NT_H = H / TH, NT_W = W / TW, NT_D = D / TD;  // 10, 24, 4
constexpr int TILES_PER_MAP = NT_H * NT_W * NT_D;           // 960
constexpr int NBLOCKS = 3 * TILES_PER_MAP;                  // 2880
constexpr int SAMPLES_PER_TILE = TH * TW * TD;              // 5120
constexpr int NTHREADS = 512;
constexpr int ITERS = SAMPLES_PER_TILE / NTHREADS;          // 10

__device__ __forceinline__ float corner_load(const float* __restrict__ vol,
                                             int ix, int iy, int iz) {
    bool valid = ((unsigned)ix < (unsigned)H) &
                 ((unsigned)iy < (unsigned)W) &
                 ((unsigned)iz < (unsigned)D);
    int cx = min(max(ix, 0), H - 1);
    int cy = min(max(iy, 0), W - 1);
    int cz = min(max(iz, 0), D - 1);
    float v = __ldg(vol + (long)cx * WD + cy * D + cz);
    return valid ? v : 0.0f;
}

__global__ __launch_bounds__(NTHREADS, 2)
void warp3d_tiled_kernel(const float* __restrict__ xin,
                         const float* __restrict__ win,
                         float* __restrict__ out) {
    extern __shared__ float smem[];

    int b = blockIdx.x;
    int n  = b / TILES_PER_MAP;
    int tr = b % TILES_PER_MAP;
    int td  = tr % NT_D;
    int twt = (tr / NT_D) % NT_W;
    int tht = tr / (NT_D * NT_W);

    int h0 = tht * TH;
    int w0 = twt * TW;
    int d0 = td * TD;
    int zb = d0 - 8;                 // staged z base, multiple of 4

    const float* vol = xin + (long)n * HWD;
    const float* fw  = win + (long)n * 3 * HWD;

    int tid = threadIdx.x;

    // ---- Stage 24x16x56 neighborhood as float4 chunks. Chunks with any OOB
    //      element are zeroed; they are never consumed by the fast path
    //      (global_ok guarantees all 8 corners are in-volume, and all
    //      in-volume voxels inside the window are staged correctly).
    constexpr int NCHUNK = SH * SW * (SD / 4);    // 5376
    for (int c = tid; c < NCHUNK; c += NTHREADS) {
        int k  = c % (SD / 4);
        int yy = (c / (SD / 4)) % SW;
        int xx = c / ((SD / 4) * SW);
        int gx = h0 - HALO + xx;
        int gy = w0 - HALO + yy;
        int gz = zb + 4 * k;
        bool ok = ((unsigned)gx < (unsigned)H) &
                  ((unsigned)gy < (unsigned)W) &
                  (gz >= 0) & (gz + 3 < D);
        float4 v = make_float4(0.f, 0.f, 0.f, 0.f);
        if (ok) v = *(const float4*)(vol + (long)gx * WD + gy * D + gz);
        *(float4*)(smem + xx * SXS + yy * SYS + 4 * k) = v;
    }
    __syncthreads();

    // ---- Sample loop: lanes get consecutive d (coalesced flow/out, spread
    //      smem banks).
    #pragma unroll
    for (int i = 0; i < ITERS; i++) {
        int s  = i * NTHREADS + tid;
        int dd = s % TD;
        int ww = (s / TD) % TW;
        int hh = s / (TD * TW);

        int h = h0 + hh, wv = w0 + ww, d = d0 + dd;
        long off = (long)h * WD + wv * D + d;

        float cx = (float)h  + __ldg(fw + off);
        float cy = (float)wv + __ldg(fw + HWD + off);
        float cz = (float)d  + __ldg(fw + 2L * HWD + off);

        float x0f = floorf(cx), y0f = floorf(cy), z0f = floorf(cz);
        float fx = cx - x0f, fy = cy - y0f, fz = cz - z0f;
        int x0 = (int)x0f, y0 = (int)y0f, z0 = (int)z0f;
        float gx0 = 1.0f - fx, gy0 = 1.0f - fy, gz0 = 1.0f - fz;

        int xr = x0 - (h0 - HALO);
        int yr = y0 - (w0 - HALO);
        int zr = z0 - zb;
        bool global_ok = ((unsigned)x0 < (unsigned)(H - 1)) &
                         ((unsigned)y0 < (unsigned)(W - 1)) &
                         ((unsigned)z0 < (unsigned)(D - 1));
        bool tile_ok = ((unsigned)xr < (unsigned)(SH - 1)) &
                       ((unsigned)yr < (unsigned)(SW - 1)) &
                       ((unsigned)zr < (unsigned)(SD - 1));

        float v000, v001, v010, v011, v100, v101, v110, v111;
        if (global_ok & tile_ok) {
            const float* p = smem + xr * SXS + yr * SYS + zr;
            v000 = p[0];
            v001 = p[1];
            v010 = p[SYS];
            v011 = p[SYS + 1];
            v100 = p[SXS];
            v101 = p[SXS + 1];
            v110 = p[SXS + SYS];
            v111 = p[SXS + SYS + 1];
        } else {
            int x1 = x0 + 1, y1 = y0 + 1, z1 = z0 + 1;
            v000 = corner_load(vol, x0, y0, z0);
            v001 = corner_load(vol, x0, y0, z1);
            v010 = corner_load(vol, x0, y1, z0);
            v011 = corner_load(vol, x0, y1, z1);
            v100 = corner_load(vol, x1, y0, z0);
            v101 = corner_load(vol, x1, y0, z1);
            v110 = corner_load(vol, x1, y1, z0);
            v111 = corner_load(vol, x1, y1, z1);
        }

        float c00 = v000 * gz0 + v001 * fz;
        float c01 = v010 * gz0 + v011 * fz;
        float c10 = v100 * gz0 + v101 * fz;
        float c11 = v110 * gz0 + v111 * fz;
        float c0  = c00 * gy0 + c01 * fy;
        float c1  = c10 * gy0 + c11 * fy;
        out[(long)n * HWD + off] = c0 * gx0 + c1 * fx;
    }
}

extern "C" void kernel_launch(void* const* d_in, const int* in_sizes, int n_in,
                              void* d_out, int out_size) {
    const float* x = (const float*)d_in[0];
    const float* w = (const float*)d_in[1];
    // x has 3*HWD elements, w has 9*HWD; swap defensively if order differs.
    if (n_in >= 2 && in_sizes[0] > in_sizes[1]) {
        const float* tmp = x; x = w; w = tmp;
    }
    float* out = (float*)d_out;

    cudaFuncSetAttribute(warp3d_tiled_kernel,
                         cudaFuncAttributeMaxDynamicSharedMemorySize,
                         SMEM_BYTES);
    warp3d_tiled_kernel<<<NBLOCKS, NTHREADS, SMEM_BYTES>>>(x, w, out);
}

// round 10
// speedup vs baseline: 3.3144x; 1.1967x over previous
#include <cuda_runtime.h>

// Warp3d: out[n, h, w, d] = trilinear_sample(x[n], grid + flow[n]),
// zeros padding, per the JAX reference. fp32 throughout.
//
// R10 (= R9 resubmit; R9 hit an infra failure): 16x8x32 tile staged as
// 24x16x44 = 66.8KB smem -> 3 blocks/SM (48 warps, 75% occ), warps aligned
// to d-rows (TD=32), fully unrolled sample loop.

constexpr int H = 160, W = 192, D = 160;
constexpr int WD  = W * D;           // 30720
constexpr int HWD = H * WD;          // 4915200

constexpr int TH = 16, TW = 8, TD = 32;
constexpr int HALO = 4;
constexpr int SH = TH + 2 * HALO;    // 24
constexpr int SW = TW + 2 * HALO;    // 16
constexpr int SD = 44;               // z coverage [d0-4, d0+39]
constexpr int SYS = SD;              // y stride (floats)
constexpr int SXS = SW * SD + 8;     // x stride = 712 (mod 32 = 8)
constexpr int SMEM_FLOATS = SH * SXS;          // 17088
constexpr int SMEM_BYTES  = SMEM_FLOATS * 4;   // 68352 (~66.8 KB)

constexpr int NT_H = H / TH, NT_W = W / TW, NT_D = D / TD;  // 10, 24, 5
constexpr int TILES_PER_MAP = NT_H * NT_W * NT_D;           // 1200
constexpr int NBLOCKS = 3 * TILES_PER_MAP;                  // 3600
constexpr int SAMPLES_PER_TILE = TH * TW * TD;              // 4096
constexpr int NTHREADS = 512;
constexpr int ITERS = SAMPLES_PER_TILE / NTHREADS;          // 8

__device__ __forceinline__ float corner_load(const float* __restrict__ vol,
                                             int ix, int iy, int iz) {
    bool valid = ((unsigned)ix < (unsigned)H) &
                 ((unsigned)iy < (unsigned)W) &
                 ((unsigned)iz < (unsigned)D);
    int cx = min(max(ix, 0), H - 1);
    int cy = min(max(iy, 0), W - 1);
    int cz = min(max(iz, 0), D - 1);
    float v = __ldg(vol + (long)cx * WD + cy * D + cz);
    return valid ? v : 0.0f;
}

__global__ __launch_bounds__(NTHREADS, 3)
void warp3d_tiled_kernel(const float* __restrict__ xin,
                         const float* __restrict__ win,
                         float* __restrict__ out) {
    extern __shared__ float smem[];

    int b = blockIdx.x;
    int n  = b / TILES_PER_MAP;
    int tr = b % TILES_PER_MAP;
    int td  = tr % NT_D;
    int twt = (tr / NT_D) % NT_W;
    int tht = tr / (NT_D * NT_W);

    int h0 = tht * TH;
    int w0 = twt * TW;
    int d0 = td * TD;
    int zb = d0 - 4;                 // staged z base, multiple of 4

    const float* vol = xin + (long)n * HWD;
    const float* fw  = win + (long)n * 3 * HWD;

    int tid = threadIdx.x;

    // ---- Stage 24x16x44 neighborhood as float4 chunks. zb and D are
    //      multiples of 4, so chunks are either fully inside or fully outside
    //      in z; OOB chunks are zeroed and never consumed by the fast path.
    constexpr int NCHUNK = SH * SW * (SD / 4);    // 4224
    for (int c = tid; c < NCHUNK; c += NTHREADS) {
        int k  = c % (SD / 4);
        int yy = (c / (SD / 4)) % SW;
        int xx = c / ((SD / 4) * SW);
        int gx = h0 - HALO + xx;
        int gy = w0 - HALO + yy;
        int gz = zb + 4 * k;
        bool ok = ((unsigned)gx < (unsigned)H) &
                  ((unsigned)gy < (unsigned)W) &
                  ((unsigned)gz < (unsigned)D);     // gz mult of 4 => gz+3 < D
        float4 v = make_float4(0.f, 0.f, 0.f, 0.f);
        if (ok) v = *(const float4*)(vol + (long)gx * WD + gy * D + gz);
        *(float4*)(smem + xx * SXS + yy * SYS + 4 * k) = v;
    }
    __syncthreads();

    // ---- Sample loop: TD=32 => each warp owns one d-row (coalesced flow/out,
    //      spread smem banks). Fully unrolled for ILP.
    #pragma unroll
    for (int i = 0; i < ITERS; i++) {
        int s  = i * NTHREADS + tid;
        int dd = s & 31;
        int ww = (s >> 5) & 7;
        int hh = s >> 8;

        int h = h0 + hh, wv = w0 + ww, d = d0 + dd;
        long off = (long)h * WD + wv * D + d;

        float cx = (float)h  + __ldg(fw + off);
        float cy = (float)wv + __ldg(fw + HWD + off);
        float cz = (float)d  + __ldg(fw + 2L * HWD + off);

        float x0f = floorf(cx), y0f = floorf(cy), z0f = floorf(cz);
        float fx = cx - x0f, fy = cy - y0f, fz = cz - z0f;
        int x0 = (int)x0f, y0 = (int)y0f, z0 = (int)z0f;
        float gx0 = 1.0f - fx, gy0 = 1.0f - fy, gz0 = 1.0f - fz;

        int xr = x0 - (h0 - HALO);
        int yr = y0 - (w0 - HALO);
        int zr = z0 - zb;
        bool global_ok = ((unsigned)x0 < (unsigned)(H - 1)) &
                         ((unsigned)y0 < (unsigned)(W - 1)) &
                         ((unsigned)z0 < (unsigned)(D - 1));
        bool tile_ok = ((unsigned)xr < (unsigned)(SH - 1)) &
                       ((unsigned)yr < (unsigned)(SW - 1)) &
                       ((unsigned)zr < (unsigned)(SD - 1));

        float v000, v001, v010, v011, v100, v101, v110, v111;
        if (global_ok & tile_ok) {
            const float* p = smem + xr * SXS + yr * SYS + zr;
            v000 = p[0];
            v001 = p[1];
            v010 = p[SYS];
            v011 = p[SYS + 1];
            v100 = p[SXS];
            v101 = p[SXS + 1];
            v110 = p[SXS + SYS];
            v111 = p[SXS + SYS + 1];
        } else {
            int x1 = x0 + 1, y1 = y0 + 1, z1 = z0 + 1;
            v000 = corner_load(vol, x0, y0, z0);
            v001 = corner_load(vol, x0, y0, z1);
            v010 = corner_load(vol, x0, y1, z0);
            v011 = corner_load(vol, x0, y1, z1);
            v100 = corner_load(vol, x1, y0, z0);
            v101 = corner_load(vol, x1, y0, z1);
            v110 = corner_load(vol, x1, y1, z0);
            v111 = corner_load(vol, x1, y1, z1);
        }

        float c00 = v000 * gz0 + v001 * fz;
        float c01 = v010 * gz0 + v011 * fz;
        float c10 = v100 * gz0 + v101 * fz;
        float c11 = v110 * gz0 + v111 * fz;
        float c0  = c00 * gy0 + c01 * fy;
        float c1  = c10 * gy0 + c11 * fy;
        out[(long)n * HWD + off] = c0 * gx0 + c1 * fx;
    }
}

extern "C" void kernel_launch(void* const* d_in, const int* in_sizes, int n_in,
                              void* d_out, int out_size) {
    const float* x = (const float*)d_in[0];
    const float* w = (const float*)d_in[1];
    // x has 3*HWD elements, w has 9*HWD; swap defensively if order differs.
    if (n_in >= 2 && in_sizes[0] > in_sizes[1]) {
        const float* tmp = x; x = w; w = tmp;
    }
    float* out = (float*)d_out;

    cudaFuncSetAttribute(warp3d_tiled_kernel,
                         cudaFuncAttributeMaxDynamicSharedMemorySize,
                         SMEM_BYTES);
    warp3d_tiled_kernel<<<NBLOCKS, NTHREADS, SMEM_BYTES>>>(x, w, out);
}

// round 12
// speedup vs baseline: 3.6913x; 1.1137x over previous
#include <cuda_runtime.h>

// Warp3d: out[n, h, w, d] = trilinear_sample(x[n], grid + flow[n]),
// zeros padding, per the JAX reference. fp32 throughout.
//
// R12 (= R11 resubmit; R11 hit an infra failure): R10 (occ 68%, issue 48%)
// is latency-bound; DRAM already at the compulsory-traffic floor. Drive
// occupancy to 100%: 8x8x32 tile staged as 16x16x44 = 44.5KB smem ->
// 4 blocks x 512 threads = 2048 threads/SM (64 warps) at the 32-register
// budget. Per-thread dd/ww are loop-invariant; hh steps by 2 per iteration.

constexpr int H = 160, W = 192, D = 160;
constexpr int WD  = W * D;           // 30720
constexpr int HWD = H * WD;          // 4915200

constexpr int TH = 8, TW = 8, TD = 32;
constexpr int HALO = 4;
constexpr int SH = TH + 2 * HALO;    // 16
constexpr int SW = TW + 2 * HALO;    // 16
constexpr int SD = 44;               // z coverage [d0-4, d0+39]
constexpr int SYS = SD;              // y stride (floats) = 44
constexpr int SXS = SW * SD + 8;     // x stride = 712 (mod 32 = 8)
constexpr int SMEM_FLOATS = SH * SXS;          // 11392
constexpr int SMEM_BYTES  = SMEM_FLOATS * 4;   // 45568 (~44.5 KB)

constexpr int NT_H = H / TH, NT_W = W / TW, NT_D = D / TD;  // 20, 24, 5
constexpr int TILES_PER_MAP = NT_H * NT_W * NT_D;           // 2400
constexpr int NBLOCKS = 3 * TILES_PER_MAP;                  // 7200
constexpr int NTHREADS = 512;
constexpr int ITERS = (TH * TW * TD) / NTHREADS;            // 4

__device__ __forceinline__ float corner_load(const float* __restrict__ vol,
                                             int ix, int iy, int iz) {
    bool valid = ((unsigned)ix < (unsigned)H) &
                 ((unsigned)iy < (unsigned)W) &
                 ((unsigned)iz < (unsigned)D);
    int cx = min(max(ix, 0), H - 1);
    int cy = min(max(iy, 0), W - 1);
    int cz = min(max(iz, 0), D - 1);
    float v = __ldg(vol + (long)cx * WD + cy * D + cz);
    return valid ? v : 0.0f;
}

__global__ __launch_bounds__(NTHREADS, 4)
void warp3d_tiled_kernel(const float* __restrict__ xin,
                         const float* __restrict__ win,
                         float* __restrict__ out) {
    extern __shared__ float smem[];

    int b = blockIdx.x;
    int n  = b / TILES_PER_MAP;
    int tr = b % TILES_PER_MAP;
    int td  = tr % NT_D;
    int twt = (tr / NT_D) % NT_W;
    int tht = tr / (NT_D * NT_W);

    int h0 = tht * TH;
    int w0 = twt * TW;
    int d0 = td * TD;
    int zb = d0 - 4;                 // staged z base, multiple of 4

    const float* vol = xin + (long)n * HWD;
    const float* fw  = win + (long)n * 3 * HWD;

    int tid = threadIdx.x;

    // ---- Stage 16x16x44 neighborhood as float4 chunks. zb and D are
    //      multiples of 4, so chunks are fully inside or fully outside in z;
    //      OOB chunks are zeroed and never consumed by the fast path.
    constexpr int NCHUNK = SH * SW * (SD / 4);    // 2816
    for (int c = tid; c < NCHUNK; c += NTHREADS) {
        int k  = c % (SD / 4);
        int yy = (c / (SD / 4)) % SW;
        int xx = c / ((SD / 4) * SW);
        int gx = h0 - HALO + xx;
        int gy = w0 - HALO + yy;
        int gz = zb + 4 * k;
        bool ok = ((unsigned)gx < (unsigned)H) &
                  ((unsigned)gy < (unsigned)W) &
                  ((unsigned)gz < (unsigned)D);     // gz mult of 4 => gz+3 < D
        float4 v = make_float4(0.f, 0.f, 0.f, 0.f);
        if (ok) v = *(const float4*)(vol + (long)gx * WD + gy * D + gz);
        *(float4*)(smem + xx * SXS + yy * SYS + 4 * k) = v;
    }
    __syncthreads();

    // ---- Sample loop. dd, ww fixed per thread; hh = (tid>>8) + 2*i.
    int dd = tid & 31;
    int ww = (tid >> 5) & 7;
    int hh = tid >> 8;               // 0 or 1

    int d  = d0 + dd;
    int wv = w0 + ww;
    long off = (long)(h0 + hh) * WD + wv * D + d;
    float fwv = (float)wv, fd = (float)d;

    #pragma unroll
    for (int i = 0; i < ITERS; i++) {
        int h = h0 + hh;

        float cx = (float)h + __ldg(fw + off);
        float cy = fwv      + __ldg(fw + HWD + off);
        float cz = fd       + __ldg(fw + 2L * HWD + off);

        float x0f = floorf(cx), y0f = floorf(cy), z0f = floorf(cz);
        float fx = cx - x0f, fy = cy - y0f, fz = cz - z0f;
        int x0 = (int)x0f, y0 = (int)y0f, z0 = (int)z0f;
        float gx0 = 1.0f - fx, gy0 = 1.0f - fy, gz0 = 1.0f - fz;

        int xr = x0 - (h0 - HALO);
        int yr = y0 - (w0 - HALO);
        int zr = z0 - zb;
        bool global_ok = ((unsigned)x0 < (unsigned)(H - 1)) &
                         ((unsigned)y0 < (unsigned)(W - 1)) &
                         ((unsigned)z0 < (unsigned)(D - 1));
        bool tile_ok = ((unsigned)xr < (unsigned)(SH - 1)) &
                       ((unsigned)yr < (unsigned)(SW - 1)) &
                       ((unsigned)zr < (unsigned)(SD - 1));

        float v000, v001, v010, v011, v100, v101, v110, v111;
        if (global_ok & tile_ok) {
            const float* p = smem + xr * SXS + yr * SYS + zr;
            v000 = p[0];
            v001 = p[1];
            v010 = p[SYS];
            v011 = p[SYS + 1];
            v100 = p[SXS];
            v101 = p[SXS + 1];
            v110 = p[SXS + SYS];
            v111 = p[SXS + SYS + 1];
        } else {
            int x1 = x0 + 1, y1 = y0 + 1, z1 = z0 + 1;
            v000 = corner_load(vol, x0, y0, z0);
            v001 = corner_load(vol, x0, y0, z1);
            v010 = corner_load(vol, x0, y1, z0);
            v011 = corner_load(vol, x0, y1, z1);
            v100 = corner_load(vol, x1, y0, z0);
            v101 = corner_load(vol, x1, y0, z1);
            v110 = corner_load(vol, x1, y1, z0);
            v111 = corner_load(vol, x1, y1, z1);
        }

        float c00 = v000 * gz0 + v001 * fz;
        float c01 = v010 * gz0 + v011 * fz;
        float c10 = v100 * gz0 + v101 * fz;
        float c11 = v110 * gz0 + v111 * fz;
        float c0  = c00 * gy0 + c01 * fy;
        float c1  = c10 * gy0 + c11 * fy;
        out[(long)n * HWD + off] = c0 * gx0 + c1 * fx;

        hh += 2;
        off += 2L * WD;
    }
}

extern "C" void kernel_launch(void* const* d_in, const int* in_sizes, int n_in,
                              void* d_out, int out_size) {
    const float* x = (const float*)d_in[0];
    const float* w = (const float*)d_in[1];
    // x has 3*HWD elements, w has 9*HWD; swap defensively if order differs.
    if (n_in >= 2 && in_sizes[0] > in_sizes[1]) {
        const float* tmp = x; x = w; w = tmp;
    }
    float* out = (float*)d_out;

    cudaFuncSetAttribute(warp3d_tiled_kernel,
                         cudaFuncAttributeMaxDynamicSharedMemorySize,
                         SMEM_BYTES);
    warp3d_tiled_kernel<<<NBLOCKS, NTHREADS, SMEM_BYTES>>>(x, w, out);
}

// round 17
// speedup vs baseline: 4.3303x; 1.1731x over previous
#include <cuda_runtime.h>
#include <cstdint>

// Warp3d: out[n, h, w, d] = trilinear_sample(x[n], grid + flow[n]),
// zeros padding, per the JAX reference. fp32 throughout.
//
// R16: R12 (110.6us, best) is L1tex-bound (78.6%); the staging LDG+STS
// round-trip is ~11 of ~25 L1 wavefronts per warp-group. Replace it with
// cp.async (LDGSTS): one LSU op per 16B chunk, no register round-trip,
// hardware zero-fill via the src_size operand. No TMA/driver plumbing.

constexpr int H = 160, W = 192, D = 160;
constexpr int WD  = W * D;           // 30720
constexpr int HWD = H * WD;          // 4915200

constexpr int TH = 8, TW = 8, TD = 32;
constexpr int HALO = 4;
constexpr int SH = TH + 2 * HALO;    // 16
constexpr int SW = TW + 2 * HALO;    // 16
constexpr int SD = 44;               // z coverage [d0-4, d0+39]
constexpr int SYS = SD;              // y stride (floats) = 44
constexpr int SXS = SW * SD + 8;     // x stride = 712 (mod 32 = 8)
constexpr int SMEM_FLOATS = SH * SXS;          // 11392
constexpr int SMEM_BYTES  = SMEM_FLOATS * 4;   // 45568 (~44.5 KB)

constexpr int NT_H = H / TH, NT_W = W / TW, NT_D = D / TD;  // 20, 24, 5
constexpr int TILES_PER_MAP = NT_H * NT_W * NT_D;           // 2400
constexpr int NBLOCKS = 3 * TILES_PER_MAP;                  // 7200
constexpr int NTHREADS = 512;
constexpr int ITERS = (TH * TW * TD) / NTHREADS;            // 4

__device__ __forceinline__ uint32_t smem_u32(const void* p) {
    uint32_t a;
    asm("{ .reg .u64 t; cvta.to.shared.u64 t, %1; cvt.u32.u64 %0, t; }"
        : "=r"(a) : "l"(p));
    return a;
}

__device__ __forceinline__ float corner_load(const float* __restrict__ vol,
                                             int ix, int iy, int iz) {
    bool valid = ((unsigned)ix < (unsigned)H) &
                 ((unsigned)iy < (unsigned)W) &
                 ((unsigned)iz < (unsigned)D);
    int cx = min(max(ix, 0), H - 1);
    int cy = min(max(iy, 0), W - 1);
    int cz = min(max(iz, 0), D - 1);
    float v = __ldg(vol + (long)cx * WD + cy * D + cz);
    return valid ? v : 0.0f;
}

__global__ __launch_bounds__(NTHREADS, 4)
void warp3d_cpasync_kernel(const float* __restrict__ xin,
                           const float* __restrict__ win,
                           float* __restrict__ out) {
    extern __shared__ float smem[];

    int b = blockIdx.x;
    int n  = b / TILES_PER_MAP;
    int tr = b % TILES_PER_MAP;
    int td  = tr % NT_D;
    int twt = (tr / NT_D) % NT_W;
    int tht = tr / (NT_D * NT_W);

    int h0 = tht * TH;
    int w0 = twt * TW;
    int d0 = td * TD;
    int zb = d0 - 4;                 // staged z base, multiple of 4

    const float* vol = xin + (long)n * HWD;
    const float* fw  = win + (long)n * 3 * HWD;

    int tid = threadIdx.x;

    // ---- Stage 16x16x44 neighborhood with cp.async 16B chunks.
    //      OOB chunks: src clamped to a valid address, src_size = 0
    //      -> hardware zero-fill (zfill idiom). zb and D are multiples of 4,
    //      so chunks are fully inside or fully outside in z.
    constexpr int NCHUNK = SH * SW * (SD / 4);    // 2816
    for (int c = tid; c < NCHUNK; c += NTHREADS) {
        int k  = c % (SD / 4);
        int yy = (c / (SD / 4)) % SW;
        int xx = c / ((SD / 4) * SW);
        int gx = h0 - HALO + xx;
        int gy = w0 - HALO + yy;
        int gz = zb + 4 * k;
        bool ok = ((unsigned)gx < (unsigned)H) &
                  ((unsigned)gy < (unsigned)W) &
                  ((unsigned)gz < (unsigned)D);     // gz mult of 4 => gz+3 < D
        const float* src = ok ? (vol + (long)gx * WD + gy * D + gz) : vol;
        int szb = ok ? 16 : 0;
        uint32_t dst = smem_u32(smem + xx * SXS + yy * SYS + 4 * k);
        asm volatile("cp.async.cg.shared.global [%0], [%1], 16, %2;"
                     :: "r"(dst), "l"(src), "r"(szb) : "memory");
    }
    asm volatile("cp.async.commit_group;" ::: "memory");
    asm volatile("cp.async.wait_group 0;" ::: "memory");
    __syncthreads();

    // ---- Sample loop. dd, ww fixed per thread; hh = (tid>>8) + 2*i.
    int dd = tid & 31;
    int ww = (tid >> 5) & 7;
    int hh = tid >> 8;               // 0 or 1

    int d  = d0 + dd;
    int wv = w0 + ww;
    long off = (long)(h0 + hh) * WD + wv * D + d;
    float fwv = (float)wv, fd = (float)d;

    #pragma unroll
    for (int i = 0; i < ITERS; i++) {
        int h = h0 + hh;

        float cx = (float)h + __ldg(fw + off);
        float cy = fwv      + __ldg(fw + HWD + off);
        float cz = fd       + __ldg(fw + 2L * HWD + off);

        float x0f = floorf(cx), y0f = floorf(cy), z0f = floorf(cz);
        float fx = cx - x0f, fy = cy - y0f, fz = cz - z0f;
        int x0 = (int)x0f, y0 = (int)y0f, z0 = (int)z0f;
        float gx0 = 1.0f - fx, gy0 = 1.0f - fy, gz0 = 1.0f - fz;

        int xr = x0 - (h0 - HALO);
        int yr = y0 - (w0 - HALO);
        int zr = z0 - zb;
        bool global_ok = ((unsigned)x0 < (unsigned)(H - 1)) &
                         ((unsigned)y0 < (unsigned)(W - 1)) &
                         ((unsigned)z0 < (unsigned)(D - 1));
        bool tile_ok = ((unsigned)xr < (unsigned)(SH - 1)) &
                       ((unsigned)yr < (unsigned)(SW - 1)) &
                       ((unsigned)zr < (unsigned)(SD - 1));

        float v000, v001, v010, v011, v100, v101, v110, v111;
        if (global_ok & tile_ok) {
            const float* p = smem + xr * SXS + yr * SYS + zr;
            v000 = p[0];
            v001 = p[1];
            v010 = p[SYS];
            v011 = p[SYS + 1];
            v100 = p[SXS];
            v101 = p[SXS + 1];
            v110 = p[SXS + SYS];
            v111 = p[SXS + SYS + 1];
        } else {
            int x1 = x0 + 1, y1 = y0 + 1, z1 = z0 + 1;
            v000 = corner_load(vol, x0, y0, z0);
            v001 = corner_load(vol, x0, y0, z1);
            v010 = corner_load(vol, x0, y1, z0);
            v011 = corner_load(vol, x0, y1, z1);
            v100 = corner_load(vol, x1, y0, z0);
            v101 = corner_load(vol, x1, y0, z1);
            v110 = corner_load(vol, x1, y1, z0);
            v111 = corner_load(vol, x1, y1, z1);
        }

        float c00 = v000 * gz0 + v001 * fz;
        float c01 = v010 * gz0 + v011 * fz;
        float c10 = v100 * gz0 + v101 * fz;
        float c11 = v110 * gz0 + v111 * fz;
        float c0  = c00 * gy0 + c01 * fy;
        float c1  = c10 * gy0 + c11 * fy;
        out[(long)n * HWD + off] = c0 * gx0 + c1 * fx;

        hh += 2;
        off += 2L * WD;
    }
}

extern "C" void kernel_launch(void* const* d_in, const int* in_sizes, int n_in,
                              void* d_out, int out_size) {
    const float* x = (const float*)d_in[0];
    const float* w = (const float*)d_in[1];
    // x has 3*HWD elements, w has 9*HWD; swap defensively if order differs.
    if (n_in >= 2 && in_sizes[0] > in_sizes[1]) {
        const float* tmp = x; x = w; w = tmp;
    }
    float* out = (float*)d_out;

    cudaFuncSetAttribute(warp3d_cpasync_kernel,
                         cudaFuncAttributeMaxDynamicSharedMemorySize,
                         SMEM_BYTES);
    warp3d_cpasync_kernel<<<NBLOCKS, NTHREADS, SMEM_BYTES>>>(x, w, out);
}